// round 16
// baseline (speedup 1.0000x reference)
#include <cuda_runtime.h>
#include <cuda_bf16.h>
#include <math.h>
#include <stdint.h>

#define N_EMB 12544
#define M_BANK 16384
#define DIM 1536
#define BATCH 16
#define PPI 784
#define KNN 9

// ---- Phase A tiling (int8 mma.m16n8k32), 2 CTAs/SM, BK=128 ----
#define BM 128
#define BN 128
#define BK 128
#define KTILES (DIM / BK)          // 12
#define NSTAGE 3
#define STRIDE_B 144               // 128 data + 16 pad -> conflict-free ldmatrix
#define A_BYTES (BM * STRIDE_B)
#define B_BYTES (BN * STRIDE_B)
#define STAGE_BYTES (A_BYTES + B_BYTES)   // 36864
#define SMEM_BYTES (NSTAGE * STAGE_BYTES) // 110592
#define GRIDX (N_EMB / BM)         // 98
#define GRIDY (M_BANK / BN)        // 128
#define SWG 8

#define QSCALE 23.0f

// ---- scan kernels: staged layout, 3 chunk buffers ----
#define QS_FLOATS (16 * DIM)             // 24576 floats = 96 KB
#define CH_FLOATS 4096                   // 128 cols x 32 dims = 16 KB
#define CH_BYTES  16384
#define NCHUNK (DIM / 32)                // 48
#define QS2_BYTES ((QS_FLOATS + 3 * CH_FLOATS) * 4)   // 147456

// ---------------- scratch ----------------
__device__ char  g_E8[N_EMB * DIM];
__device__ char  g_M8[M_BANK * DIM];
__device__ int   g_ynq[M_BANK];
__device__ unsigned long long g_minpack[N_EMB];
__device__ unsigned long long g_nnpack[BATCH];
__device__ unsigned long long g_maxpack[BATCH];   // (fkey(score) << 32) | (PPI-1-p)
__device__ float g_xnorm[N_EMB];
__device__ float g_ynorm[M_BANK];
__device__ float g_d2[BATCH * M_BANK];

__device__ __forceinline__ unsigned fkey(float f) {
    unsigned u = __float_as_uint(f);
    return (u & 0x80000000u) ? ~u : (u | 0x80000000u);
}
__device__ __forceinline__ float unkey(unsigned k) {
    unsigned u = (k & 0x80000000u) ? (k ^ 0x80000000u) : ~k;
    return __uint_as_float(u);
}

__device__ __forceinline__ void cpasync16(uint32_t dst, const void* src) {
    asm volatile("cp.async.cg.shared.global [%0], [%1], 16;" :: "r"(dst), "l"(src));
}
__device__ __forceinline__ void ldsm4(uint32_t* r, uint32_t addr) {
    asm volatile("ldmatrix.sync.aligned.m8n8.x4.shared.b16 {%0,%1,%2,%3}, [%4];"
                 : "=r"(r[0]), "=r"(r[1]), "=r"(r[2]), "=r"(r[3]) : "r"(addr));
}
__device__ __forceinline__ void mma_s8(int* c, const uint32_t* a, uint32_t b0, uint32_t b1) {
    asm volatile("mma.sync.aligned.m16n8k32.row.col.s32.s8.s8.s32 "
                 "{%0,%1,%2,%3}, {%4,%5,%6,%7}, {%8,%9}, {%0,%1,%2,%3};"
                 : "+r"(c[0]), "+r"(c[1]), "+r"(c[2]), "+r"(c[3])
                 : "r"(a[0]), "r"(a[1]), "r"(a[2]), "r"(a[3]), "r"(b0), "r"(b1));
}

__device__ __forceinline__ int q8(float x) {
    int v = __float2int_rn(x * QSCALE);
    return max(-127, min(127, v));
}

// ---------------- fused convert-to-int8 + norms + scratch init ----------------
__global__ void convert_norms_kernel(const float* __restrict__ E, const float* __restrict__ Mb) {
    int row = blockIdx.x;
    const bool isE = row < N_EMB;
    const float* p = isE ? (E + (size_t)row * DIM) : (Mb + (size_t)(row - N_EMB) * DIM);
    char* q = isE ? (g_E8 + (size_t)row * DIM) : (g_M8 + (size_t)(row - N_EMB) * DIM);
    float s = 0.f;
    int   sq = 0;
    for (int i = threadIdx.x; i < DIM / 4; i += blockDim.x) {
        float4 v = ((const float4*)p)[i];
        s += v.x * v.x + v.y * v.y + v.z * v.z + v.w * v.w;
        int a = q8(v.x), b = q8(v.y), c = q8(v.z), d = q8(v.w);
        sq += a * a + b * b + c * c + d * d;
        uint32_t pk = (uint32_t)(a & 0xff) | ((uint32_t)(b & 0xff) << 8) |
                      ((uint32_t)(c & 0xff) << 16) | ((uint32_t)(d & 0xff) << 24);
        ((uint32_t*)q)[i] = pk;
    }
#pragma unroll
    for (int o = 16; o; o >>= 1) {
        s  += __shfl_down_sync(0xffffffffu, s, o);
        sq += __shfl_down_sync(0xffffffffu, sq, o);
    }
    __shared__ float ws[4];
    __shared__ int   wq[4];
    if ((threadIdx.x & 31) == 0) { ws[threadIdx.x >> 5] = s; wq[threadIdx.x >> 5] = sq; }
    __syncthreads();
    if (threadIdx.x == 0) {
        float t = ws[0] + ws[1] + ws[2] + ws[3];
        int   ti = wq[0] + wq[1] + wq[2] + wq[3];
        if (isE) {
            g_xnorm[row] = t;
            g_minpack[row] = 0xFFFFFFFFFFFFFFFFull;
            if (row < BATCH) { g_nnpack[row] = 0xFFFFFFFFFFFFFFFFull; g_maxpack[row] = 0ull; }
        } else {
            g_ynorm[row - N_EMB] = t; g_ynq[row - N_EMB] = ti;
        }
    }
}

// ---------------- Phase A: int8 tensor-core dist-argmin GEMM ----------------
__global__ void __launch_bounds__(256, 2) distmin_s8() {
    extern __shared__ char dsm[];
    const int tid = threadIdx.x;
    const int lane = tid & 31, warp = tid >> 5;
    const int wr = warp & 3, wc = warp >> 2;

    const int band = blockIdx.x / (GRIDX * SWG);
    const int rem  = blockIdx.x % (GRIDX * SWG);
    const int by   = band * SWG + (rem % SWG);
    const int bx   = rem / SWG;
    const int rowBase = bx * BM;
    const int colBase = by * BN;

    uint32_t sbase = (uint32_t)__cvta_generic_to_shared(dsm);

    const char* src[8];
    uint32_t dsto[8];
#pragma unroll
    for (int i = 0; i < 8; i++) {
        int idx = tid + i * 256;
        if (idx < 1024) {
            int row = idx >> 3, c = idx & 7;
            src[i]  = g_E8 + (size_t)(rowBase + row) * DIM + c * 16;
            dsto[i] = row * STRIDE_B + c * 16;
        } else {
            int j = idx - 1024;
            int row = j >> 3, c = j & 7;
            src[i]  = g_M8 + (size_t)(colBase + row) * DIM + c * 16;
            dsto[i] = A_BYTES + row * STRIDE_B + c * 16;
        }
    }

    const int arow = (lane & 7) + ((lane >> 3) & 1) * 8;
    const uint32_t akb = (lane >> 4) * 16;
    uint32_t aAddr[2];
#pragma unroll
    for (int m = 0; m < 2; m++)
        aAddr[m] = sbase + (wr * 32 + m * 16 + arow) * STRIDE_B + akb;
    const int brow = (lane & 7) + (lane >> 4) * 8;
    const uint32_t bkb = ((lane >> 3) & 1) * 16;
    uint32_t bAddr[4];
#pragma unroll
    for (int g = 0; g < 4; g++)
        bAddr[g] = sbase + A_BYTES + (wc * 64 + g * 16 + brow) * STRIDE_B + bkb;

    int acc[2][8][4];
#pragma unroll
    for (int m = 0; m < 2; m++)
#pragma unroll
        for (int t = 0; t < 8; t++)
#pragma unroll
            for (int c = 0; c < 4; c++) acc[m][t][c] = 0;

#pragma unroll
    for (int s = 0; s < NSTAGE - 1; s++) {
#pragma unroll
        for (int i = 0; i < 8; i++) cpasync16(sbase + s * STAGE_BYTES + dsto[i], src[i] + s * BK);
        asm volatile("cp.async.commit_group;");
    }

#pragma unroll
    for (int kt = 0; kt < KTILES; kt++) {
        const int st = kt % NSTAGE;
        asm volatile("cp.async.wait_group %0;" :: "n"(NSTAGE - 2));
        __syncthreads();
        if (kt + NSTAGE - 1 < KTILES) {
            const int ps = (kt + NSTAGE - 1) % NSTAGE;
            const int ko = (kt + NSTAGE - 1) * BK;
#pragma unroll
            for (int i = 0; i < 8; i++) cpasync16(sbase + ps * STAGE_BYTES + dsto[i], src[i] + ko);
            asm volatile("cp.async.commit_group;");
        }
        const uint32_t so = st * STAGE_BYTES;
#pragma unroll
        for (int s = 0; s < 4; s++) {
            uint32_t af[2][4], bf[4][4];
#pragma unroll
            for (int m = 0; m < 2; m++) ldsm4(af[m], aAddr[m] + so + s * 32);
#pragma unroll
            for (int g = 0; g < 4; g++) ldsm4(bf[g], bAddr[g] + so + s * 32);
#pragma unroll
            for (int m = 0; m < 2; m++)
#pragma unroll
                for (int t = 0; t < 8; t++)
                    mma_s8(acc[m][t], af[m], bf[t >> 1][(t & 1) * 2], bf[t >> 1][(t & 1) * 2 + 1]);
        }
    }
    __syncthreads();

    const int gid = lane >> 2, qid = lane & 3;
    unsigned long long* red = (unsigned long long*)dsm;
#pragma unroll
    for (int m = 0; m < 2; m++)
#pragma unroll
        for (int h = 0; h < 2; h++) {
            int bv = 0x7fffffff;
            int bj = 0x7fffffff;
#pragma unroll
            for (int t = 0; t < 8; t++)
#pragma unroll
                for (int c = 0; c < 2; c++) {
                    int col = colBase + wc * 64 + t * 8 + qid * 2 + c;
                    int q = g_ynq[col] - 2 * acc[m][t][h * 2 + c];
                    if (q < bv || (q == bv && col < bj)) { bv = q; bj = col; }
                }
#pragma unroll
            for (int off = 1; off < 4; off <<= 1) {
                int ov = __shfl_xor_sync(0xffffffffu, bv, off, 4);
                int oj = __shfl_xor_sync(0xffffffffu, bj, off, 4);
                if (ov < bv || (ov == bv && oj < bj)) { bv = ov; bj = oj; }
            }
            if (qid == 0) {
                int rloc = wr * 32 + m * 16 + h * 8 + gid;
                unsigned ku = (unsigned)bv ^ 0x80000000u;
                red[wc * 128 + rloc] = ((unsigned long long)ku << 32) | (unsigned)bj;
            }
        }
    __syncthreads();
    if (tid < BM) {
        unsigned long long p = red[tid];
        unsigned long long q1 = red[128 + tid]; if (q1 < p) p = q1;
        atomicMin(&g_minpack[rowBase + tid], p);
    }
}

// ---------------- exact fp32 rescore + fused per-image argmax ----------------
__global__ void rescore_kernel(const float* __restrict__ E, const float* __restrict__ Mb) {
    int warp = threadIdx.x >> 5, lane = threadIdx.x & 31;
    int row = blockIdx.x * 8 + warp;
    int col = (int)(g_minpack[row] & 0xffffffffull);
    const float4* x = (const float4*)(E + (size_t)row * DIM);
    const float4* y = (const float4*)(Mb + (size_t)col * DIM);
    float s = 0.f;
    for (int i = lane; i < DIM / 4; i += 32) {
        float4 a = x[i], b = y[i];
        s += a.x * b.x + a.y * b.y + a.z * b.z + a.w * b.w;
    }
#pragma unroll
    for (int o = 16; o; o >>= 1) s += __shfl_down_sync(0xffffffffu, s, o);
    if (lane == 0) {
        float d2 = g_xnorm[row] + g_ynorm[col] - 2.f * s;
        float sc = sqrtf(fmaxf(d2, 0.f));
        int b = row / PPI, p = row % PPI;
        unsigned long long pk = ((unsigned long long)fkey(sc) << 32) | (unsigned)(PPI - 1 - p);
        atomicMax(&g_maxpack[b], pk);
    }
}

// ---------------- exact fp32 NN search for the 16 argmax rows ----------------
// 512 = 64 col-slots x 8 D-groups; Mb streamed via 3-buffered 16KB chunks; scalar FMA
__global__ void __launch_bounds__(512) exactnn_kernel(const float* __restrict__ E,
                                                      const float* __restrict__ Mb) {
    extern __shared__ float Qs[];          // queries + 3 chunk bufs
    float* CS = Qs + QS_FLOATS;
    __shared__ int qr[16];
    __shared__ unsigned long long part[16];
    const int tid = threadIdx.x;
    const int s = tid & 63, g = tid >> 6;
    const int colBase0 = blockIdx.x * 128;
    const uint32_t csBase = (uint32_t)__cvta_generic_to_shared(CS);
    const int c0 = tid >> 3, j0 = tid & 7;
    const int c1 = (tid + 512) >> 3, j1 = tid & 7;
    const uint32_t d0off = c0 * 128 + (((j0 + c0) & 7) << 4);
    const uint32_t d1off = c1 * 128 + (((j1 + c1) & 7) << 4);
    const float* s0 = Mb + (size_t)(colBase0 + c0) * DIM + j0 * 4;
    const float* s1 = Mb + (size_t)(colBase0 + c1) * DIM + j1 * 4;

    if (tid < 16) {
        int p = PPI - 1 - (int)(g_maxpack[tid] & 0xffffffffull);
        qr[tid] = tid * PPI + p;
        part[tid] = 0xFFFFFFFFFFFFFFFFull;
    }
    // prologue: stage chunks 0,1
#pragma unroll
    for (int pc = 0; pc < 2; pc++) {
        cpasync16(csBase + pc * CH_BYTES + d0off, s0 + pc * 32);
        cpasync16(csBase + pc * CH_BYTES + d1off, s1 + pc * 32);
        asm volatile("cp.async.commit_group;");
    }
    __syncthreads();   // qr visible for Q staging
    for (int i = tid; i < QS_FLOATS / 4; i += 512) {
        int q = i / 384, d4 = i % 384;
        ((float4*)Qs)[i] = ((const float4*)(E + (size_t)qr[q] * DIM))[d4];
    }

    float acc0[16], acc1[16];
#pragma unroll
    for (int q = 0; q < 16; q++) { acc0[q] = 0.f; acc1[q] = 0.f; }
    const uint32_t sw = ((g + s) & 7) << 4;
    const char* v0base = (const char*)CS + s * 128 + sw;
    const char* v1base = (const char*)CS + (s + 64) * 128 + sw;

    for (int ch = 0; ch < NCHUNK; ch++) {
        const int buf = ch % 3;
        if (ch + 1 < NCHUNK) asm volatile("cp.async.wait_group 1;");
        else                 asm volatile("cp.async.wait_group 0;");
        __syncthreads();     // chunk ch visible; buffer (ch+2)%3 fully drained
        if (ch + 2 < NCHUNK) {
            const int nb = (ch + 2) % 3;
            cpasync16(csBase + nb * CH_BYTES + d0off, s0 + (ch + 2) * 32);
            cpasync16(csBase + nb * CH_BYTES + d1off, s1 + (ch + 2) * 32);
            asm volatile("cp.async.commit_group;");
        }
        float4 v0 = *(const float4*)(v0base + buf * CH_BYTES);
        float4 v1 = *(const float4*)(v1base + buf * CH_BYTES);
        const float4* Qb = ((const float4*)Qs) + ch * 8 + g;
#pragma unroll
        for (int q = 0; q < 16; q++) {
            float4 u = Qb[q * 384];
            acc0[q] = fmaf(v0.x, u.x, fmaf(v0.y, u.y, fmaf(v0.z, u.z, fmaf(v0.w, u.w, acc0[q]))));
            acc1[q] = fmaf(v1.x, u.x, fmaf(v1.y, u.y, fmaf(v1.z, u.z, fmaf(v1.w, u.w, acc1[q]))));
        }
    }
    __syncthreads();   // all Q reads done; reuse Qs as reduction buffer

    float* red = Qs;                       // red[qc*512 + g*64 + s], 64 KB
#pragma unroll
    for (int q = 0; q < 16; q++) {
        red[q * 512 + g * 64 + s]        = acc0[q];
        red[(16 + q) * 512 + g * 64 + s] = acc1[q];
    }
    __syncthreads();
    if (g == 0) {
        const int col0 = colBase0 + s, col1 = col0 + 64;
        float yn0 = g_ynorm[col0], yn1 = g_ynorm[col1];
#pragma unroll
        for (int q = 0; q < 16; q++) {
            float d0 = 0.f, d1 = 0.f;
#pragma unroll
            for (int gg = 0; gg < 8; gg++) {
                d0 += red[q * 512 + gg * 64 + s];
                d1 += red[(16 + q) * 512 + gg * 64 + s];
            }
            float xn = g_xnorm[qr[q]];
            float e0 = xn + yn0 - 2.f * d0;
            float e1 = xn + yn1 - 2.f * d1;
            atomicMin(&part[q], ((unsigned long long)fkey(e0) << 32) | (unsigned)col0);
            atomicMin(&part[q], ((unsigned long long)fkey(e1) << 32) | (unsigned)col1);
        }
    }
    __syncthreads();
    if (tid < 16) atomicMin(&g_nnpack[tid], part[tid]);
}

// ---------------- Phase C1: d^2 from 16 nn_samples to all memory rows ----------------
__global__ void __launch_bounds__(512) knn_dist_kernel(const float* __restrict__ Mb) {
    extern __shared__ float Qs[];
    float* CS = Qs + QS_FLOATS;
    __shared__ int nn[16];
    __shared__ float qn[16];
    const int tid = threadIdx.x;
    const int s = tid & 63, g = tid >> 6;
    const int colBase0 = blockIdx.x * 128;
    const uint32_t csBase = (uint32_t)__cvta_generic_to_shared(CS);
    const int c0 = tid >> 3, j0 = tid & 7;
    const int c1 = (tid + 512) >> 3, j1 = tid & 7;
    const uint32_t d0off = c0 * 128 + (((j0 + c0) & 7) << 4);
    const uint32_t d1off = c1 * 128 + (((j1 + c1) & 7) << 4);
    const float* s0 = Mb + (size_t)(colBase0 + c0) * DIM + j0 * 4;
    const float* s1 = Mb + (size_t)(colBase0 + c1) * DIM + j1 * 4;

    if (tid < 16) {
        int idx = (int)(g_nnpack[tid] & 0xffffffffull);
        nn[tid] = idx; qn[tid] = g_ynorm[idx];
    }
#pragma unroll
    for (int pc = 0; pc < 2; pc++) {
        cpasync16(csBase + pc * CH_BYTES + d0off, s0 + pc * 32);
        cpasync16(csBase + pc * CH_BYTES + d1off, s1 + pc * 32);
        asm volatile("cp.async.commit_group;");
    }
    __syncthreads();
    for (int i = tid; i < QS_FLOATS / 4; i += 512) {
        int q = i / 384, d4 = i % 384;
        ((float4*)Qs)[i] = ((const float4*)(Mb + (size_t)nn[q] * DIM))[d4];
    }

    float acc0[16], acc1[16];
#pragma unroll
    for (int q = 0; q < 16; q++) { acc0[q] = 0.f; acc1[q] = 0.f; }
    const uint32_t sw = ((g + s) & 7) << 4;
    const char* v0base = (const char*)CS + s * 128 + sw;
    const char* v1base = (const char*)CS + (s + 64) * 128 + sw;

    for (int ch = 0; ch < NCHUNK; ch++) {
        const int buf = ch % 3;
        if (ch + 1 < NCHUNK) asm volatile("cp.async.wait_group 1;");
        else                 asm volatile("cp.async.wait_group 0;");
        __syncthreads();
        if (ch + 2 < NCHUNK) {
            const int nb = (ch + 2) % 3;
            cpasync16(csBase + nb * CH_BYTES + d0off, s0 + (ch + 2) * 32);
            cpasync16(csBase + nb * CH_BYTES + d1off, s1 + (ch + 2) * 32);
            asm volatile("cp.async.commit_group;");
        }
        float4 v0 = *(const float4*)(v0base + buf * CH_BYTES);
        float4 v1 = *(const float4*)(v1base + buf * CH_BYTES);
        const float4* Qb = ((const float4*)Qs) + ch * 8 + g;
#pragma unroll
        for (int q = 0; q < 16; q++) {
            float4 u = Qb[q * 384];
            acc0[q] = fmaf(v0.x, u.x, fmaf(v0.y, u.y, fmaf(v0.z, u.z, fmaf(v0.w, u.w, acc0[q]))));
            acc1[q] = fmaf(v1.x, u.x, fmaf(v1.y, u.y, fmaf(v1.z, u.z, fmaf(v1.w, u.w, acc1[q]))));
        }
    }
    __syncthreads();

    float* red = Qs;
#pragma unroll
    for (int q = 0; q < 16; q++) {
        red[q * 512 + g * 64 + s]        = acc0[q];
        red[(16 + q) * 512 + g * 64 + s] = acc1[q];
    }
    __syncthreads();
    if (g == 0) {
        const int col0 = colBase0 + s, col1 = col0 + 64;
        float yn0 = g_ynorm[col0], yn1 = g_ynorm[col1];
#pragma unroll
        for (int q = 0; q < 16; q++) {
            float d0 = 0.f, d1 = 0.f;
#pragma unroll
            for (int gg = 0; gg < 8; gg++) {
                d0 += red[q * 512 + gg * 64 + s];
                d1 += red[(16 + q) * 512 + gg * 64 + s];
            }
            g_d2[q * M_BANK + col0] = qn[q] + yn0 - 2.f * d0;
            g_d2[q * M_BANK + col1] = qn[q] + yn1 - 2.f * d1;
        }
    }
}

// ---------------- Phase C2 + D: stable top-9, distances, softmax, output ----------------
__global__ void top9_final_kernel(const float* __restrict__ E, const float* __restrict__ Mb,
                                  float* __restrict__ out) {
    int b = blockIdx.x;
    int tid = threadIdx.x;
    float v[9]; int id[9];
#pragma unroll
    for (int k = 0; k < 9; k++) { v[k] = __int_as_float(0x7f800000); id[k] = 0x7fffffff; }
    for (int j = tid; j < M_BANK; j += 128) {
        float d = g_d2[b * M_BANK + j];
        if (d < v[8] || (d == v[8] && j < id[8])) {
            int k = 8;
            while (k > 0 && (d < v[k - 1] || (d == v[k - 1] && j < id[k - 1]))) {
                v[k] = v[k - 1]; id[k] = id[k - 1]; k--;
            }
            v[k] = d; id[k] = j;
        }
    }
    __shared__ float svv[128 * 9];
    __shared__ int   sid[128 * 9];
    __shared__ int   s_sup[9];
    __shared__ float s_ds[9];
    __shared__ float s_red[4];
#pragma unroll
    for (int k = 0; k < 9; k++) { svv[tid * 9 + k] = v[k]; sid[tid * 9 + k] = id[k]; }
    __syncthreads();
    if (tid == 0) {
        float fv[9]; int fid[9];
#pragma unroll
        for (int k = 0; k < 9; k++) { fv[k] = __int_as_float(0x7f800000); fid[k] = 0x7fffffff; }
        for (int t = 0; t < 128; t++) {
            for (int k = 0; k < 9; k++) {
                float d = svv[t * 9 + k]; int j = sid[t * 9 + k];
                if (d > fv[8] || (d == fv[8] && j >= fid[8])) break;
                int m = 8;
                while (m > 0 && (d < fv[m - 1] || (d == fv[m - 1] && j < fid[m - 1]))) {
                    fv[m] = fv[m - 1]; fid[m] = fid[m - 1]; m--;
                }
                fv[m] = d; fid[m] = j;
            }
        }
        for (int k = 0; k < 9; k++) s_sup[k] = fid[k];
    }
    __syncthreads();

    unsigned long long mp = g_maxpack[b];
    int maxrow = b * PPI + (PPI - 1 - (int)(mp & 0xffffffffull));
    const float4* x = (const float4*)(E + (size_t)maxrow * DIM);
    for (int k = 0; k < 9; k++) {
        const float4* y = (const float4*)(Mb + (size_t)s_sup[k] * DIM);
        float s = 0.f;
        for (int i = tid; i < 384; i += 128) {
            float4 xv = x[i], yv = y[i];
            float dx = xv.x - yv.x, dy = xv.y - yv.y, dz = xv.z - yv.z, dw = xv.w - yv.w;
            s += dx * dx + dy * dy + dz * dz + dw * dw;
        }
#pragma unroll
        for (int o = 16; o; o >>= 1) s += __shfl_down_sync(0xffffffffu, s, o);
        if ((tid & 31) == 0) s_red[tid >> 5] = s;
        __syncthreads();
        if (tid == 0) s_ds[k] = sqrtf(fmaxf(s_red[0] + s_red[1] + s_red[2] + s_red[3], 0.f));
        __syncthreads();
    }
    if (tid == 0) {
        float m = s_ds[0];
        for (int k = 1; k < 9; k++) m = fmaxf(m, s_ds[k]);
        float sum = 0.f, e0 = 0.f;
        for (int k = 0; k < 9; k++) {
            float e = expf(s_ds[k] - m);
            if (k == 0) e0 = e;
            sum += e;
        }
        out[b] = (1.f - e0 / sum) * unkey((unsigned)(mp >> 32));
    }
}

// ---------------- launch ----------------
extern "C" void kernel_launch(void* const* d_in, const int* in_sizes, int n_in,
                              void* d_out, int out_size) {
    const float* E  = (const float*)d_in[0];
    const float* Mb = (const float*)d_in[1];
    float* out = (float*)d_out;

    cudaFuncSetAttribute(distmin_s8, cudaFuncAttributeMaxDynamicSharedMemorySize, SMEM_BYTES);
    cudaFuncSetAttribute(exactnn_kernel, cudaFuncAttributeMaxDynamicSharedMemorySize, QS2_BYTES);
    cudaFuncSetAttribute(knn_dist_kernel, cudaFuncAttributeMaxDynamicSharedMemorySize, QS2_BYTES);

    convert_norms_kernel<<<N_EMB + M_BANK, 128>>>(E, Mb);
    distmin_s8<<<GRIDX * GRIDY, 256, SMEM_BYTES>>>();
    rescore_kernel<<<N_EMB / 8, 256>>>(E, Mb);
    exactnn_kernel<<<M_BANK / 128, 512, QS2_BYTES>>>(E, Mb);
    knn_dist_kernel<<<M_BANK / 128, 512, QS2_BYTES>>>(Mb);
    top9_final_kernel<<<BATCH, 128>>>(E, Mb, out);
}

// round 17
// speedup vs baseline: 1.0121x; 1.0121x over previous
#include <cuda_runtime.h>
#include <cuda_bf16.h>
#include <math.h>
#include <stdint.h>

#define N_EMB 12544
#define M_BANK 16384
#define DIM 1536
#define BATCH 16
#define PPI 784
#define KNN 9

// ---- Phase A tiling (int8 mma.m16n8k32), 2 CTAs/SM, BK=128 ----
#define BM 128
#define BN 128
#define BK 128
#define KTILES (DIM / BK)          // 12
#define NSTAGE 3
#define STRIDE_B 144               // 128 data + 16 pad -> conflict-free ldmatrix
#define A_BYTES (BM * STRIDE_B)
#define B_BYTES (BN * STRIDE_B)
#define STAGE_BYTES (A_BYTES + B_BYTES)   // 36864
#define SMEM_BYTES (NSTAGE * STAGE_BYTES) // 110592
#define GRIDX (N_EMB / BM)         // 98
#define GRIDY (M_BANK / BN)        // 128
#define SWG 8

#define QSCALE 23.0f

// ---- scan kernels: staged layout, 3 chunk-PAIR buffers ----
#define QS_FLOATS (16 * DIM)             // 24576 floats = 96 KB
#define CH_FLOATS 4096                   // 128 cols x 32 dims = 16 KB
#define CH_BYTES  16384
#define NCHUNK (DIM / 32)                // 48
#define NPAIR (NCHUNK / 2)               // 24
#define QS2_BYTES ((QS_FLOATS + 6 * CH_FLOATS) * 4)   // 196608 (96K Q + 96K bufs)

// ---------------- scratch ----------------
__device__ char  g_E8[N_EMB * DIM];
__device__ char  g_M8[M_BANK * DIM];
__device__ int   g_ynq[M_BANK];
__device__ unsigned long long g_minpack[N_EMB];
__device__ unsigned long long g_nnpack[BATCH];
__device__ unsigned long long g_maxpack[BATCH];   // (fkey(score) << 32) | (PPI-1-p)
__device__ float g_xnorm[N_EMB];
__device__ float g_ynorm[M_BANK];
__device__ float g_d2[BATCH * M_BANK];

__device__ __forceinline__ unsigned fkey(float f) {
    unsigned u = __float_as_uint(f);
    return (u & 0x80000000u) ? ~u : (u | 0x80000000u);
}
__device__ __forceinline__ float unkey(unsigned k) {
    unsigned u = (k & 0x80000000u) ? (k ^ 0x80000000u) : ~k;
    return __uint_as_float(u);
}

__device__ __forceinline__ void cpasync16(uint32_t dst, const void* src) {
    asm volatile("cp.async.cg.shared.global [%0], [%1], 16;" :: "r"(dst), "l"(src));
}
__device__ __forceinline__ void ldsm4(uint32_t* r, uint32_t addr) {
    asm volatile("ldmatrix.sync.aligned.m8n8.x4.shared.b16 {%0,%1,%2,%3}, [%4];"
                 : "=r"(r[0]), "=r"(r[1]), "=r"(r[2]), "=r"(r[3]) : "r"(addr));
}
__device__ __forceinline__ void mma_s8(int* c, const uint32_t* a, uint32_t b0, uint32_t b1) {
    asm volatile("mma.sync.aligned.m16n8k32.row.col.s32.s8.s8.s32 "
                 "{%0,%1,%2,%3}, {%4,%5,%6,%7}, {%8,%9}, {%0,%1,%2,%3};"
                 : "+r"(c[0]), "+r"(c[1]), "+r"(c[2]), "+r"(c[3])
                 : "r"(a[0]), "r"(a[1]), "r"(a[2]), "r"(a[3]), "r"(b0), "r"(b1));
}

__device__ __forceinline__ int q8(float x) {
    int v = __float2int_rn(x * QSCALE);
    return max(-127, min(127, v));
}

// ---------------- fused convert-to-int8 + norms + scratch init ----------------
__global__ void convert_norms_kernel(const float* __restrict__ E, const float* __restrict__ Mb) {
    int row = blockIdx.x;
    const bool isE = row < N_EMB;
    const float* p = isE ? (E + (size_t)row * DIM) : (Mb + (size_t)(row - N_EMB) * DIM);
    char* q = isE ? (g_E8 + (size_t)row * DIM) : (g_M8 + (size_t)(row - N_EMB) * DIM);
    float s = 0.f;
    int   sq = 0;
    for (int i = threadIdx.x; i < DIM / 4; i += blockDim.x) {
        float4 v = ((const float4*)p)[i];
        s += v.x * v.x + v.y * v.y + v.z * v.z + v.w * v.w;
        int a = q8(v.x), b = q8(v.y), c = q8(v.z), d = q8(v.w);
        sq += a * a + b * b + c * c + d * d;
        uint32_t pk = (uint32_t)(a & 0xff) | ((uint32_t)(b & 0xff) << 8) |
                      ((uint32_t)(c & 0xff) << 16) | ((uint32_t)(d & 0xff) << 24);
        ((uint32_t*)q)[i] = pk;
    }
#pragma unroll
    for (int o = 16; o; o >>= 1) {
        s  += __shfl_down_sync(0xffffffffu, s, o);
        sq += __shfl_down_sync(0xffffffffu, sq, o);
    }
    __shared__ float ws[4];
    __shared__ int   wq[4];
    if ((threadIdx.x & 31) == 0) { ws[threadIdx.x >> 5] = s; wq[threadIdx.x >> 5] = sq; }
    __syncthreads();
    if (threadIdx.x == 0) {
        float t = ws[0] + ws[1] + ws[2] + ws[3];
        int   ti = wq[0] + wq[1] + wq[2] + wq[3];
        if (isE) {
            g_xnorm[row] = t;
            g_minpack[row] = 0xFFFFFFFFFFFFFFFFull;
            if (row < BATCH) { g_nnpack[row] = 0xFFFFFFFFFFFFFFFFull; g_maxpack[row] = 0ull; }
        } else {
            g_ynorm[row - N_EMB] = t; g_ynq[row - N_EMB] = ti;
        }
    }
}

// ---------------- Phase A: int8 tensor-core dist-argmin GEMM ----------------
__global__ void __launch_bounds__(256, 2) distmin_s8() {
    extern __shared__ char dsm[];
    const int tid = threadIdx.x;
    const int lane = tid & 31, warp = tid >> 5;
    const int wr = warp & 3, wc = warp >> 2;

    const int band = blockIdx.x / (GRIDX * SWG);
    const int rem  = blockIdx.x % (GRIDX * SWG);
    const int by   = band * SWG + (rem % SWG);
    const int bx   = rem / SWG;
    const int rowBase = bx * BM;
    const int colBase = by * BN;

    uint32_t sbase = (uint32_t)__cvta_generic_to_shared(dsm);

    const char* src[8];
    uint32_t dsto[8];
#pragma unroll
    for (int i = 0; i < 8; i++) {
        int idx = tid + i * 256;
        if (idx < 1024) {
            int row = idx >> 3, c = idx & 7;
            src[i]  = g_E8 + (size_t)(rowBase + row) * DIM + c * 16;
            dsto[i] = row * STRIDE_B + c * 16;
        } else {
            int j = idx - 1024;
            int row = j >> 3, c = j & 7;
            src[i]  = g_M8 + (size_t)(colBase + row) * DIM + c * 16;
            dsto[i] = A_BYTES + row * STRIDE_B + c * 16;
        }
    }

    const int arow = (lane & 7) + ((lane >> 3) & 1) * 8;
    const uint32_t akb = (lane >> 4) * 16;
    uint32_t aAddr[2];
#pragma unroll
    for (int m = 0; m < 2; m++)
        aAddr[m] = sbase + (wr * 32 + m * 16 + arow) * STRIDE_B + akb;
    const int brow = (lane & 7) + (lane >> 4) * 8;
    const uint32_t bkb = ((lane >> 3) & 1) * 16;
    uint32_t bAddr[4];
#pragma unroll
    for (int g = 0; g < 4; g++)
        bAddr[g] = sbase + A_BYTES + (wc * 64 + g * 16 + brow) * STRIDE_B + bkb;

    int acc[2][8][4];
#pragma unroll
    for (int m = 0; m < 2; m++)
#pragma unroll
        for (int t = 0; t < 8; t++)
#pragma unroll
            for (int c = 0; c < 4; c++) acc[m][t][c] = 0;

#pragma unroll
    for (int s = 0; s < NSTAGE - 1; s++) {
#pragma unroll
        for (int i = 0; i < 8; i++) cpasync16(sbase + s * STAGE_BYTES + dsto[i], src[i] + s * BK);
        asm volatile("cp.async.commit_group;");
    }

#pragma unroll
    for (int kt = 0; kt < KTILES; kt++) {
        const int st = kt % NSTAGE;
        asm volatile("cp.async.wait_group %0;" :: "n"(NSTAGE - 2));
        __syncthreads();
        if (kt + NSTAGE - 1 < KTILES) {
            const int ps = (kt + NSTAGE - 1) % NSTAGE;
            const int ko = (kt + NSTAGE - 1) * BK;
#pragma unroll
            for (int i = 0; i < 8; i++) cpasync16(sbase + ps * STAGE_BYTES + dsto[i], src[i] + ko);
            asm volatile("cp.async.commit_group;");
        }
        const uint32_t so = st * STAGE_BYTES;
#pragma unroll
        for (int s = 0; s < 4; s++) {
            uint32_t af[2][4], bf[4][4];
#pragma unroll
            for (int m = 0; m < 2; m++) ldsm4(af[m], aAddr[m] + so + s * 32);
#pragma unroll
            for (int g = 0; g < 4; g++) ldsm4(bf[g], bAddr[g] + so + s * 32);
#pragma unroll
            for (int m = 0; m < 2; m++)
#pragma unroll
                for (int t = 0; t < 8; t++)
                    mma_s8(acc[m][t], af[m], bf[t >> 1][(t & 1) * 2], bf[t >> 1][(t & 1) * 2 + 1]);
        }
    }
    __syncthreads();

    const int gid = lane >> 2, qid = lane & 3;
    unsigned long long* red = (unsigned long long*)dsm;
#pragma unroll
    for (int m = 0; m < 2; m++)
#pragma unroll
        for (int h = 0; h < 2; h++) {
            int bv = 0x7fffffff;
            int bj = 0x7fffffff;
#pragma unroll
            for (int t = 0; t < 8; t++)
#pragma unroll
                for (int c = 0; c < 2; c++) {
                    int col = colBase + wc * 64 + t * 8 + qid * 2 + c;
                    int q = g_ynq[col] - 2 * acc[m][t][h * 2 + c];
                    if (q < bv || (q == bv && col < bj)) { bv = q; bj = col; }
                }
#pragma unroll
            for (int off = 1; off < 4; off <<= 1) {
                int ov = __shfl_xor_sync(0xffffffffu, bv, off, 4);
                int oj = __shfl_xor_sync(0xffffffffu, bj, off, 4);
                if (ov < bv || (ov == bv && oj < bj)) { bv = ov; bj = oj; }
            }
            if (qid == 0) {
                int rloc = wr * 32 + m * 16 + h * 8 + gid;
                unsigned ku = (unsigned)bv ^ 0x80000000u;
                red[wc * 128 + rloc] = ((unsigned long long)ku << 32) | (unsigned)bj;
            }
        }
    __syncthreads();
    if (tid < BM) {
        unsigned long long p = red[tid];
        unsigned long long q1 = red[128 + tid]; if (q1 < p) p = q1;
        atomicMin(&g_minpack[rowBase + tid], p);
    }
}

// ---------------- exact fp32 rescore + fused per-image argmax ----------------
__global__ void rescore_kernel(const float* __restrict__ E, const float* __restrict__ Mb) {
    int warp = threadIdx.x >> 5, lane = threadIdx.x & 31;
    int row = blockIdx.x * 8 + warp;
    int col = (int)(g_minpack[row] & 0xffffffffull);
    const float4* x = (const float4*)(E + (size_t)row * DIM);
    const float4* y = (const float4*)(Mb + (size_t)col * DIM);
    float s = 0.f;
    for (int i = lane; i < DIM / 4; i += 32) {
        float4 a = x[i], b = y[i];
        s += a.x * b.x + a.y * b.y + a.z * b.z + a.w * b.w;
    }
#pragma unroll
    for (int o = 16; o; o >>= 1) s += __shfl_down_sync(0xffffffffu, s, o);
    if (lane == 0) {
        float d2 = g_xnorm[row] + g_ynorm[col] - 2.f * s;
        float sc = sqrtf(fmaxf(d2, 0.f));
        int b = row / PPI, p = row % PPI;
        unsigned long long pk = ((unsigned long long)fkey(sc) << 32) | (unsigned)(PPI - 1 - p);
        atomicMax(&g_maxpack[b], pk);
    }
}

// ---------------- exact fp32 NN search for the 16 argmax rows ----------------
// 512 = 64 col-slots x 8 D-groups; Mb streamed via 3 chunk-pair buffers; scalar FMA
__global__ void __launch_bounds__(512) exactnn_kernel(const float* __restrict__ E,
                                                      const float* __restrict__ Mb) {
    extern __shared__ float Qs[];          // queries + 6 chunk bufs
    float* CS = Qs + QS_FLOATS;
    __shared__ int qr[16];
    __shared__ unsigned long long part[16];
    const int tid = threadIdx.x;
    const int s = tid & 63, g = tid >> 6;
    const int colBase0 = blockIdx.x * 128;
    const uint32_t csBase = (uint32_t)__cvta_generic_to_shared(CS);
    const int c0 = tid >> 3, j0 = tid & 7;
    const int c1 = (tid + 512) >> 3, j1 = tid & 7;
    const uint32_t d0off = c0 * 128 + (((j0 + c0) & 7) << 4);
    const uint32_t d1off = c1 * 128 + (((j1 + c1) & 7) << 4);
    const float* s0 = Mb + (size_t)(colBase0 + c0) * DIM + j0 * 4;
    const float* s1 = Mb + (size_t)(colBase0 + c1) * DIM + j1 * 4;

    if (tid < 16) {
        int p = PPI - 1 - (int)(g_maxpack[tid] & 0xffffffffull);
        qr[tid] = tid * PPI + p;
        part[tid] = 0xFFFFFFFFFFFFFFFFull;
    }
    // prologue: stage pairs 0,1 (chunks 0..3); one commit per pair
#pragma unroll
    for (int pp = 0; pp < 2; pp++) {
#pragma unroll
        for (int h = 0; h < 2; h++) {
            int ch = pp * 2 + h;
            cpasync16(csBase + ch * CH_BYTES + d0off, s0 + ch * 32);
            cpasync16(csBase + ch * CH_BYTES + d1off, s1 + ch * 32);
        }
        asm volatile("cp.async.commit_group;");
    }
    __syncthreads();   // qr visible for Q staging
    for (int i = tid; i < QS_FLOATS / 4; i += 512) {
        int q = i / 384, d4 = i % 384;
        ((float4*)Qs)[i] = ((const float4*)(E + (size_t)qr[q] * DIM))[d4];
    }

    float acc0[16], acc1[16];
#pragma unroll
    for (int q = 0; q < 16; q++) { acc0[q] = 0.f; acc1[q] = 0.f; }
    const uint32_t sw = ((g + s) & 7) << 4;
    const char* v0base = (const char*)CS + s * 128 + sw;
    const char* v1base = (const char*)CS + (s + 64) * 128 + sw;

    for (int pr = 0; pr < NPAIR; pr++) {
        const int bp = pr % 3;                 // buffer pair (bufs 2bp, 2bp+1)
        if (pr + 1 < NPAIR) asm volatile("cp.async.wait_group 1;");
        else                asm volatile("cp.async.wait_group 0;");
        __syncthreads();   // pair pr visible; buffer pair (pr+2)%3 fully drained
        if (pr + 2 < NPAIR) {
            const int nb = (pr + 2) % 3;
#pragma unroll
            for (int h = 0; h < 2; h++) {
                int ch = (pr + 2) * 2 + h;
                cpasync16(csBase + (nb * 2 + h) * CH_BYTES + d0off, s0 + ch * 32);
                cpasync16(csBase + (nb * 2 + h) * CH_BYTES + d1off, s1 + ch * 32);
            }
            asm volatile("cp.async.commit_group;");
        }
#pragma unroll
        for (int h = 0; h < 2; h++) {
            const int buf = bp * 2 + h;
            const int ch = pr * 2 + h;
            float4 v0 = *(const float4*)(v0base + buf * CH_BYTES);
            float4 v1 = *(const float4*)(v1base + buf * CH_BYTES);
            const float4* Qb = ((const float4*)Qs) + ch * 8 + g;
#pragma unroll
            for (int q = 0; q < 16; q++) {
                float4 u = Qb[q * 384];
                acc0[q] = fmaf(v0.x, u.x, fmaf(v0.y, u.y, fmaf(v0.z, u.z, fmaf(v0.w, u.w, acc0[q]))));
                acc1[q] = fmaf(v1.x, u.x, fmaf(v1.y, u.y, fmaf(v1.z, u.z, fmaf(v1.w, u.w, acc1[q]))));
            }
        }
    }
    __syncthreads();   // all Q reads done; reuse Qs as reduction buffer

    float* red = Qs;                       // red[qc*512 + g*64 + s], 64 KB
#pragma unroll
    for (int q = 0; q < 16; q++) {
        red[q * 512 + g * 64 + s]        = acc0[q];
        red[(16 + q) * 512 + g * 64 + s] = acc1[q];
    }
    __syncthreads();
    if (g == 0) {
        const int col0 = colBase0 + s, col1 = col0 + 64;
        float yn0 = g_ynorm[col0], yn1 = g_ynorm[col1];
#pragma unroll
        for (int q = 0; q < 16; q++) {
            float d0 = 0.f, d1 = 0.f;
#pragma unroll
            for (int gg = 0; gg < 8; gg++) {
                d0 += red[q * 512 + gg * 64 + s];
                d1 += red[(16 + q) * 512 + gg * 64 + s];
            }
            float xn = g_xnorm[qr[q]];
            float e0 = xn + yn0 - 2.f * d0;
            float e1 = xn + yn1 - 2.f * d1;
            atomicMin(&part[q], ((unsigned long long)fkey(e0) << 32) | (unsigned)col0);
            atomicMin(&part[q], ((unsigned long long)fkey(e1) << 32) | (unsigned)col1);
        }
    }
    __syncthreads();
    if (tid < 16) atomicMin(&g_nnpack[tid], part[tid]);
}

// ---------------- Phase C1: d^2 from 16 nn_samples to all memory rows ----------------
__global__ void __launch_bounds__(512) knn_dist_kernel(const float* __restrict__ Mb) {
    extern __shared__ float Qs[];
    float* CS = Qs + QS_FLOATS;
    __shared__ int nn[16];
    __shared__ float qn[16];
    const int tid = threadIdx.x;
    const int s = tid & 63, g = tid >> 6;
    const int colBase0 = blockIdx.x * 128;
    const uint32_t csBase = (uint32_t)__cvta_generic_to_shared(CS);
    const int c0 = tid >> 3, j0 = tid & 7;
    const int c1 = (tid + 512) >> 3, j1 = tid & 7;
    const uint32_t d0off = c0 * 128 + (((j0 + c0) & 7) << 4);
    const uint32_t d1off = c1 * 128 + (((j1 + c1) & 7) << 4);
    const float* s0 = Mb + (size_t)(colBase0 + c0) * DIM + j0 * 4;
    const float* s1 = Mb + (size_t)(colBase0 + c1) * DIM + j1 * 4;

    if (tid < 16) {
        int idx = (int)(g_nnpack[tid] & 0xffffffffull);
        nn[tid] = idx; qn[tid] = g_ynorm[idx];
    }
#pragma unroll
    for (int pp = 0; pp < 2; pp++) {
#pragma unroll
        for (int h = 0; h < 2; h++) {
            int ch = pp * 2 + h;
            cpasync16(csBase + ch * CH_BYTES + d0off, s0 + ch * 32);
            cpasync16(csBase + ch * CH_BYTES + d1off, s1 + ch * 32);
        }
        asm volatile("cp.async.commit_group;");
    }
    __syncthreads();
    for (int i = tid; i < QS_FLOATS / 4; i += 512) {
        int q = i / 384, d4 = i % 384;
        ((float4*)Qs)[i] = ((const float4*)(Mb + (size_t)nn[q] * DIM))[d4];
    }

    float acc0[16], acc1[16];
#pragma unroll
    for (int q = 0; q < 16; q++) { acc0[q] = 0.f; acc1[q] = 0.f; }
    const uint32_t sw = ((g + s) & 7) << 4;
    const char* v0base = (const char*)CS + s * 128 + sw;
    const char* v1base = (const char*)CS + (s + 64) * 128 + sw;

    for (int pr = 0; pr < NPAIR; pr++) {
        const int bp = pr % 3;
        if (pr + 1 < NPAIR) asm volatile("cp.async.wait_group 1;");
        else                asm volatile("cp.async.wait_group 0;");
        __syncthreads();
        if (pr + 2 < NPAIR) {
            const int nb = (pr + 2) % 3;
#pragma unroll
            for (int h = 0; h < 2; h++) {
                int ch = (pr + 2) * 2 + h;
                cpasync16(csBase + (nb * 2 + h) * CH_BYTES + d0off, s0 + ch * 32);
                cpasync16(csBase + (nb * 2 + h) * CH_BYTES + d1off, s1 + ch * 32);
            }
            asm volatile("cp.async.commit_group;");
        }
#pragma unroll
        for (int h = 0; h < 2; h++) {
            const int buf = bp * 2 + h;
            const int ch = pr * 2 + h;
            float4 v0 = *(const float4*)(v0base + buf * CH_BYTES);
            float4 v1 = *(const float4*)(v1base + buf * CH_BYTES);
            const float4* Qb = ((const float4*)Qs) + ch * 8 + g;
#pragma unroll
            for (int q = 0; q < 16; q++) {
                float4 u = Qb[q * 384];
                acc0[q] = fmaf(v0.x, u.x, fmaf(v0.y, u.y, fmaf(v0.z, u.z, fmaf(v0.w, u.w, acc0[q]))));
                acc1[q] = fmaf(v1.x, u.x, fmaf(v1.y, u.y, fmaf(v1.z, u.z, fmaf(v1.w, u.w, acc1[q]))));
            }
        }
    }
    __syncthreads();

    float* red = Qs;
#pragma unroll
    for (int q = 0; q < 16; q++) {
        red[q * 512 + g * 64 + s]        = acc0[q];
        red[(16 + q) * 512 + g * 64 + s] = acc1[q];
    }
    __syncthreads();
    if (g == 0) {
        const int col0 = colBase0 + s, col1 = col0 + 64;
        float yn0 = g_ynorm[col0], yn1 = g_ynorm[col1];
#pragma unroll
        for (int q = 0; q < 16; q++) {
            float d0 = 0.f, d1 = 0.f;
#pragma unroll
            for (int gg = 0; gg < 8; gg++) {
                d0 += red[q * 512 + gg * 64 + s];
                d1 += red[(16 + q) * 512 + gg * 64 + s];
            }
            g_d2[q * M_BANK + col0] = qn[q] + yn0 - 2.f * d0;
            g_d2[q * M_BANK + col1] = qn[q] + yn1 - 2.f * d1;
        }
    }
}

// ---------------- Phase C2 + D: stable top-9, distances, softmax, output ----------------
__global__ void top9_final_kernel(const float* __restrict__ E, const float* __restrict__ Mb,
                                  float* __restrict__ out) {
    int b = blockIdx.x;
    int tid = threadIdx.x;
    float v[9]; int id[9];
#pragma unroll
    for (int k = 0; k < 9; k++) { v[k] = __int_as_float(0x7f800000); id[k] = 0x7fffffff; }
    for (int j = tid; j < M_BANK; j += 128) {
        float d = g_d2[b * M_BANK + j];
        if (d < v[8] || (d == v[8] && j < id[8])) {
            int k = 8;
            while (k > 0 && (d < v[k - 1] || (d == v[k - 1] && j < id[k - 1]))) {
                v[k] = v[k - 1]; id[k] = id[k - 1]; k--;
            }
            v[k] = d; id[k] = j;
        }
    }
    __shared__ float svv[128 * 9];
    __shared__ int   sid[128 * 9];
    __shared__ int   s_sup[9];
    __shared__ float s_ds[9];
    __shared__ float s_red[4];
#pragma unroll
    for (int k = 0; k < 9; k++) { svv[tid * 9 + k] = v[k]; sid[tid * 9 + k] = id[k]; }
    __syncthreads();
    if (tid == 0) {
        float fv[9]; int fid[9];
#pragma unroll
        for (int k = 0; k < 9; k++) { fv[k] = __int_as_float(0x7f800000); fid[k] = 0x7fffffff; }
        for (int t = 0; t < 128; t++) {
            for (int k = 0; k < 9; k++) {
                float d = svv[t * 9 + k]; int j = sid[t * 9 + k];
                if (d > fv[8] || (d == fv[8] && j >= fid[8])) break;
                int m = 8;
                while (m > 0 && (d < fv[m - 1] || (d == fv[m - 1] && j < fid[m - 1]))) {
                    fv[m] = fv[m - 1]; fid[m] = fid[m - 1]; m--;
                }
                fv[m] = d; fid[m] = j;
            }
        }
        for (int k = 0; k < 9; k++) s_sup[k] = fid[k];
    }
    __syncthreads();

    unsigned long long mp = g_maxpack[b];
    int maxrow = b * PPI + (PPI - 1 - (int)(mp & 0xffffffffull));
    const float4* x = (const float4*)(E + (size_t)maxrow * DIM);
    for (int k = 0; k < 9; k++) {
        const float4* y = (const float4*)(Mb + (size_t)s_sup[k] * DIM);
        float s = 0.f;
        for (int i = tid; i < 384; i += 128) {
            float4 xv = x[i], yv = y[i];
            float dx = xv.x - yv.x, dy = xv.y - yv.y, dz = xv.z - yv.z, dw = xv.w - yv.w;
            s += dx * dx + dy * dy + dz * dz + dw * dw;
        }
#pragma unroll
        for (int o = 16; o; o >>= 1) s += __shfl_down_sync(0xffffffffu, s, o);
        if ((tid & 31) == 0) s_red[tid >> 5] = s;
        __syncthreads();
        if (tid == 0) s_ds[k] = sqrtf(fmaxf(s_red[0] + s_red[1] + s_red[2] + s_red[3], 0.f));
        __syncthreads();
    }
    if (tid == 0) {
        float m = s_ds[0];
        for (int k = 1; k < 9; k++) m = fmaxf(m, s_ds[k]);
        float sum = 0.f, e0 = 0.f;
        for (int k = 0; k < 9; k++) {
            float e = expf(s_ds[k] - m);
            if (k == 0) e0 = e;
            sum += e;
        }
        out[b] = (1.f - e0 / sum) * unkey((unsigned)(mp >> 32));
    }
}

// ---------------- launch ----------------
extern "C" void kernel_launch(void* const* d_in, const int* in_sizes, int n_in,
                              void* d_out, int out_size) {
    const float* E  = (const float*)d_in[0];
    const float* Mb = (const float*)d_in[1];
    float* out = (float*)d_out;

    cudaFuncSetAttribute(distmin_s8, cudaFuncAttributeMaxDynamicSharedMemorySize, SMEM_BYTES);
    cudaFuncSetAttribute(exactnn_kernel, cudaFuncAttributeMaxDynamicSharedMemorySize, QS2_BYTES);
    cudaFuncSetAttribute(knn_dist_kernel, cudaFuncAttributeMaxDynamicSharedMemorySize, QS2_BYTES);

    convert_norms_kernel<<<N_EMB + M_BANK, 128>>>(E, Mb);
    distmin_s8<<<GRIDX * GRIDY, 256, SMEM_BYTES>>>();
    rescore_kernel<<<N_EMB / 8, 256>>>(E, Mb);
    exactnn_kernel<<<M_BANK / 128, 512, QS2_BYTES>>>(E, Mb);
    knn_dist_kernel<<<M_BANK / 128, 512, QS2_BYTES>>>(Mb);
    top9_final_kernel<<<BATCH, 128>>>(E, Mb, out);
}